// round 12
// baseline (speedup 1.0000x reference)
#include <cuda_runtime.h>
#include <cuda_fp16.h>

#define N_USERS 200000
#define N_ITEMS 100000
#define N_NODES 300000
#define N_EDGES 1500000
#define DIM 64
#define BERT 384

#define SCAN_B 1024
#define NB ((N_NODES + SCAN_B - 1) / SCAN_B)   // 293

// Scratch (static device globals — no allocs).
__device__ __align__(16) __half g_hx[2][(size_t)N_NODES * DIM];  // fp16 x buffers
__device__ int   g_cnt[N_NODES];                        // degree counts -> cursors
__device__ int   g_rowptr[N_NODES + 1];
__device__ int   g_blocksum[NB];
__device__ int   g_blockoff[NB];
__device__ __align__(16) int2 g_edge[N_EDGES];          // {col, val bits}
__device__ __align__(16) unsigned g_wfrag[24 * 1024];   // W tf32, fragment order

// ---------------------------------------------------------------------------
// CSR build: zero counts -> histogram -> 2-level exclusive scan -> scatter
// ---------------------------------------------------------------------------
__global__ void zero_cnt_k()
{
    int i = blockIdx.x * blockDim.x + threadIdx.x;
    if (i < N_NODES) g_cnt[i] = 0;
}

__global__ void hist_k(const int* __restrict__ rows)
{
    int e = blockIdx.x * blockDim.x + threadIdx.x;
    if (e < N_EDGES) atomicAdd(&g_cnt[rows[e]], 1);
}

__global__ __launch_bounds__(SCAN_B) void scan1_k()
{
    __shared__ int wsum[32];
    int tid = threadIdx.x, lane = tid & 31, wid = tid >> 5;
    int i = blockIdx.x * SCAN_B + tid;
    int v = (i < N_NODES) ? g_cnt[i] : 0;
    int orig = v;
#pragma unroll
    for (int d = 1; d < 32; d <<= 1) {
        int t = __shfl_up_sync(0xFFFFFFFFu, v, d);
        if (lane >= d) v += t;
    }
    if (lane == 31) wsum[wid] = v;
    __syncthreads();
    if (wid == 0) {
        int w = wsum[lane];
#pragma unroll
        for (int d = 1; d < 32; d <<= 1) {
            int t = __shfl_up_sync(0xFFFFFFFFu, w, d);
            if (lane >= d) w += t;
        }
        wsum[lane] = w;
    }
    __syncthreads();
    int woff = wid ? wsum[wid - 1] : 0;
    int incl = v + woff;
    if (i < N_NODES) g_rowptr[i] = incl - orig;                  // exclusive in-block
    if (tid == SCAN_B - 1) g_blocksum[blockIdx.x] = incl;
}

__global__ __launch_bounds__(512) void scan2_k()
{
    __shared__ int wsum[16];
    int tid = threadIdx.x, lane = tid & 31, wid = tid >> 5;
    int v = (tid < NB) ? g_blocksum[tid] : 0;
    int orig = v;
#pragma unroll
    for (int d = 1; d < 32; d <<= 1) {
        int t = __shfl_up_sync(0xFFFFFFFFu, v, d);
        if (lane >= d) v += t;
    }
    if (lane == 31) wsum[wid] = v;
    __syncthreads();
    if (wid == 0) {
        int w = (lane < 16) ? wsum[lane] : 0;
#pragma unroll
        for (int d = 1; d < 16; d <<= 1) {
            int t = __shfl_up_sync(0xFFFFFFFFu, w, d);
            if (lane >= d) w += t;
        }
        if (lane < 16) wsum[lane] = w;
    }
    __syncthreads();
    int woff = wid ? wsum[wid - 1] : 0;
    if (tid < NB) g_blockoff[tid] = v + woff - orig;             // exclusive
    if (tid == 0) g_rowptr[N_NODES] = N_EDGES;
}

__global__ void scan3_k()
{
    int i = blockIdx.x * blockDim.x + threadIdx.x;
    if (i < N_NODES) {
        int r = g_rowptr[i] + g_blockoff[i >> 10];
        g_rowptr[i] = r;
        g_cnt[i] = r;                                            // cursor for scatter
    }
}

__global__ void scatter_k(const int* __restrict__ rows,
                          const int* __restrict__ cols,
                          const float* __restrict__ vals)
{
    int e = blockIdx.x * blockDim.x + threadIdx.x;
    if (e >= N_EDGES) return;
    int r = rows[e];
    int p = atomicAdd(&g_cnt[r], 1);
    g_edge[p] = make_int2(cols[e], __float_as_int(vals[e]));
}

// ---------------------------------------------------------------------------
// User init: out[u] = user_emb[u] + gender + age (fp32 to d_out, fp16 to g_hx[0])
// ---------------------------------------------------------------------------
__global__ void init_users_k(const float4* __restrict__ ue,
                             const float4* __restrict__ ge,
                             const float4* __restrict__ ae,
                             const int* __restrict__ ug,
                             const int* __restrict__ ua,
                             float4* __restrict__ out)
{
    int idx = blockIdx.x * blockDim.x + threadIdx.x;
    if (idx >= N_USERS * 16) return;
    int u = idx >> 4, s = idx & 15;
    int g = ug[u];
    int a = ua[u];
    float4 r = ue[idx];
    float4 gv = ge[g * 16 + s];
    float4 av = ae[a * 16 + s];
    r.x += gv.x + av.x; r.y += gv.y + av.y;
    r.z += gv.z + av.z; r.w += gv.w + av.w;
    out[idx] = r;
    __half2 h0 = __floats2half2_rn(r.x, r.y);
    __half2 h1 = __floats2half2_rn(r.z, r.w);
    uint2 p;
    p.x = *reinterpret_cast<unsigned*>(&h0);
    p.y = *reinterpret_cast<unsigned*>(&h1);
    reinterpret_cast<uint2*>(g_hx[0])[idx] = p;
}

// ---------------------------------------------------------------------------
// TF32 GEMM with fragment-ordered smem (R10, measured 65.5us) + fp16 side copy.
// ---------------------------------------------------------------------------
#define CVT_TF32(d, s) asm("cvt.rna.tf32.f32 %0, %1;" : "=r"(d) : "f"(s))

#define MMA_TF32(c, a0, a1, a2, a3, b0, b1)                                  \
    asm("mma.sync.aligned.m16n8k8.row.col.f32.tf32.tf32.f32 "               \
        "{%0,%1,%2,%3}, {%4,%5,%6,%7}, {%8,%9}, {%0,%1,%2,%3};"             \
        : "+f"((c)[0]), "+f"((c)[1]), "+f"((c)[2]), "+f"((c)[3])            \
        : "r"(a0), "r"(a1), "r"(a2), "r"(a3), "r"(b0), "r"(b1))

__global__ void wfrag_k(const float* __restrict__ W)
{
    int w = blockIdx.x * 256 + threadIdx.x;
    if (w >= 24 * 1024) return;
    int kt = w >> 10, r = w & 1023;
    int ipair = r >> 7;              // kk*4 + ntp
    int kk = ipair >> 2, ntp = ipair & 3;
    int r2 = r & 127;
    int lane = r2 >> 2, low = r2 & 3;
    int nthalf = low >> 1, reg = low & 1;
    int nt = ntp * 2 + nthalf;
    int gid = lane >> 2, tig = lane & 3;
    int n = nt * 8 + gid;
    int k = kt * 16 + kk * 8 + tig + reg * 4;
    unsigned u;
    CVT_TF32(u, W[(size_t)n * BERT + k]);
    g_wfrag[w] = u;
}

#define NKT (BERT / 16)     // 24
#define APAD 20

__global__ __launch_bounds__(128) void item_gemm_k(
    const float* __restrict__ bert,      // [N_ITEMS, 384]
    const float* __restrict__ ie,        // item_emb [N_ITEMS, 64]
    const float* __restrict__ ce,        // cat_emb [11, 64]
    const int* __restrict__ cat,
    float* __restrict__ out)
{
    __shared__ __align__(16) unsigned As[2][64 * APAD];   // [buf][m*20 + k]
    __shared__ __align__(16) uint4    Bs[2][256];          // [buf] fragment order

    int t    = threadIdx.x;
    int wid  = t >> 5;
    int lane = t & 31;
    int gid  = lane >> 2;        // 0..7
    int tig  = lane & 3;         // 0..3
    int wrow = wid * 16;
    int rb   = blockIdx.x * 64;

    float c[8][4];
#pragma unroll
    for (int nt = 0; nt < 8; nt++)
#pragma unroll
        for (int j = 0; j < 4; j++) c[nt][j] = 0.f;

    const uint4* wsrc = reinterpret_cast<const uint4*>(g_wfrag);
    float4 va[2];
    uint4  vb[2];

#define LOAD_AB(k0, kt)                                                      \
    {                                                                        \
        _Pragma("unroll")                                                    \
        for (int i = 0; i < 2; i++) {                                        \
            int q = i * 128 + t;                                             \
            int m = q >> 2, kq = q & 3;                                      \
            va[i] = (rb + m < N_ITEMS)                                       \
                ? *reinterpret_cast<const float4*>(                          \
                      bert + (size_t)(rb + m) * BERT + (k0) + kq * 4)        \
                : make_float4(0.f, 0.f, 0.f, 0.f);                           \
            vb[i] = __ldg(wsrc + (kt) * 256 + i * 128 + t);                  \
        }                                                                    \
    }
#define STORE_AB(buf)                                                        \
    {                                                                        \
        _Pragma("unroll")                                                    \
        for (int i = 0; i < 2; i++) {                                        \
            int q = i * 128 + t;                                             \
            int m = q >> 2, kq = q & 3;                                      \
            unsigned u0, u1, u2, u3;                                         \
            CVT_TF32(u0, va[i].x); CVT_TF32(u1, va[i].y);                    \
            CVT_TF32(u2, va[i].z); CVT_TF32(u3, va[i].w);                    \
            *reinterpret_cast<uint4*>(&As[buf][m * APAD + kq * 4]) =         \
                make_uint4(u0, u1, u2, u3);                                  \
            Bs[buf][i * 128 + t] = vb[i];                                    \
        }                                                                    \
    }

    LOAD_AB(0, 0);
    STORE_AB(0);
    __syncthreads();

#pragma unroll 1
    for (int kt = 0; kt < NKT; kt++) {
        int buf = kt & 1;
        if (kt + 1 < NKT) LOAD_AB((kt + 1) * 16, kt + 1);

#pragma unroll
        for (int kk = 0; kk < 2; kk++) {
            int kb = kk * 8;
            unsigned a0 = As[buf][(wrow + gid)     * APAD + kb + tig];
            unsigned a1 = As[buf][(wrow + gid + 8) * APAD + kb + tig];
            unsigned a2 = As[buf][(wrow + gid)     * APAD + kb + tig + 4];
            unsigned a3 = As[buf][(wrow + gid + 8) * APAD + kb + tig + 4];
#pragma unroll
            for (int ntp = 0; ntp < 4; ntp++) {
                uint4 bb = Bs[buf][(kk * 4 + ntp) * 32 + lane];
                MMA_TF32(c[2 * ntp],     a0, a1, a2, a3, bb.x, bb.y);
                MMA_TF32(c[2 * ntp + 1], a0, a1, a2, a3, bb.z, bb.w);
            }
        }

        if (kt + 1 < NKT) STORE_AB(buf ^ 1);
        __syncthreads();
    }

    // Epilogue: + item_emb + cat_emb; fp32 to out, fp16 copy to g_hx[0].
    int r0 = rb + wrow + gid;
    int r1 = r0 + 8;
    int cc0 = (r0 < N_ITEMS) ? cat[r0] : 0;
    int cc1 = (r1 < N_ITEMS) ? cat[r1] : 0;
    __half* hx0 = g_hx[0];
#pragma unroll
    for (int nt = 0; nt < 8; nt++) {
        int n0 = nt * 8 + tig * 2;
        if (r0 < N_ITEMS) {
            float2 e = *reinterpret_cast<const float2*>(ie + (size_t)r0 * 64 + n0);
            float2 v = *reinterpret_cast<const float2*>(ce + (size_t)cc0 * 64 + n0);
            float2 o = make_float2(c[nt][0] + e.x + v.x, c[nt][1] + e.y + v.y);
            *reinterpret_cast<float2*>(out + (size_t)(N_USERS + r0) * 64 + n0) = o;
            __half2 h = __floats2half2_rn(o.x, o.y);
            *reinterpret_cast<unsigned*>(hx0 + (size_t)(N_USERS + r0) * 64 + n0) =
                *reinterpret_cast<unsigned*>(&h);
        }
        if (r1 < N_ITEMS) {
            float2 e = *reinterpret_cast<const float2*>(ie + (size_t)r1 * 64 + n0);
            float2 v = *reinterpret_cast<const float2*>(ce + (size_t)cc1 * 64 + n0);
            float2 o = make_float2(c[nt][2] + e.x + v.x, c[nt][3] + e.y + v.y);
            *reinterpret_cast<float2*>(out + (size_t)(N_USERS + r1) * 64 + n0) = o;
            __half2 h = __floats2half2_rn(o.x, o.y);
            *reinterpret_cast<unsigned*>(hx0 + (size_t)(N_USERS + r1) * 64 + n0) =
                *reinterpret_cast<unsigned*>(&h);
        }
    }
}

// ---------------------------------------------------------------------------
// CSR gather SpMM on fp16 features: 4 lanes per row, lane owns 32B (2 uint4)
// -> 2 independent LDG.128 per edge (MLP up to 8 in the 4-edge rung).
// Compute fp32, store fp16.
// ---------------------------------------------------------------------------
__device__ __forceinline__ void acc_h(float* a, uint4 xv, float v)
{
    float2 f0 = __half22float2(*reinterpret_cast<__half2*>(&xv.x));
    float2 f1 = __half22float2(*reinterpret_cast<__half2*>(&xv.y));
    float2 f2 = __half22float2(*reinterpret_cast<__half2*>(&xv.z));
    float2 f3 = __half22float2(*reinterpret_cast<__half2*>(&xv.w));
    a[0] += v * f0.x; a[1] += v * f0.y;
    a[2] += v * f1.x; a[3] += v * f1.y;
    a[4] += v * f2.x; a[5] += v * f2.y;
    a[6] += v * f3.x; a[7] += v * f3.y;
}

__device__ __forceinline__ void spmm_row_h4(const uint4* __restrict__ x,
                                            int r, int s, float* acc /*16*/)
{
    int beg = __ldg(&g_rowptr[r]);
    int end = __ldg(&g_rowptr[r + 1]);
    int jj = beg;
    while (jj < end) {
        int n = end - jj;
        if (n >= 4) {
            int2 e0 = __ldg(&g_edge[jj + 0]);
            int2 e1 = __ldg(&g_edge[jj + 1]);
            int2 e2 = __ldg(&g_edge[jj + 2]);
            int2 e3 = __ldg(&g_edge[jj + 3]);
            uint4 p0 = __ldg(&x[e0.x * 8 + 2 * s]);
            uint4 q0 = __ldg(&x[e0.x * 8 + 2 * s + 1]);
            uint4 p1 = __ldg(&x[e1.x * 8 + 2 * s]);
            uint4 q1 = __ldg(&x[e1.x * 8 + 2 * s + 1]);
            uint4 p2 = __ldg(&x[e2.x * 8 + 2 * s]);
            uint4 q2 = __ldg(&x[e2.x * 8 + 2 * s + 1]);
            uint4 p3 = __ldg(&x[e3.x * 8 + 2 * s]);
            uint4 q3 = __ldg(&x[e3.x * 8 + 2 * s + 1]);
            float v0 = __int_as_float(e0.y);
            float v1 = __int_as_float(e1.y);
            float v2 = __int_as_float(e2.y);
            float v3 = __int_as_float(e3.y);
            acc_h(acc, p0, v0); acc_h(acc + 8, q0, v0);
            acc_h(acc, p1, v1); acc_h(acc + 8, q1, v1);
            acc_h(acc, p2, v2); acc_h(acc + 8, q2, v2);
            acc_h(acc, p3, v3); acc_h(acc + 8, q3, v3);
            jj += 4;
        } else if (n >= 2) {
            int2 e0 = __ldg(&g_edge[jj + 0]);
            int2 e1 = __ldg(&g_edge[jj + 1]);
            uint4 p0 = __ldg(&x[e0.x * 8 + 2 * s]);
            uint4 q0 = __ldg(&x[e0.x * 8 + 2 * s + 1]);
            uint4 p1 = __ldg(&x[e1.x * 8 + 2 * s]);
            uint4 q1 = __ldg(&x[e1.x * 8 + 2 * s + 1]);
            float v0 = __int_as_float(e0.y);
            float v1 = __int_as_float(e1.y);
            acc_h(acc, p0, v0); acc_h(acc + 8, q0, v0);
            acc_h(acc, p1, v1); acc_h(acc + 8, q1, v1);
            jj += 2;
        } else {
            int2 e0 = __ldg(&g_edge[jj]);
            uint4 p0 = __ldg(&x[e0.x * 8 + 2 * s]);
            uint4 q0 = __ldg(&x[e0.x * 8 + 2 * s + 1]);
            float v0 = __int_as_float(e0.y);
            acc_h(acc, p0, v0); acc_h(acc + 8, q0, v0);
            jj += 1;
        }
    }
}

__device__ __forceinline__ uint4 pack_h8(const float* a)
{
    __half2 h0 = __floats2half2_rn(a[0], a[1]);
    __half2 h1 = __floats2half2_rn(a[2], a[3]);
    __half2 h2 = __floats2half2_rn(a[4], a[5]);
    __half2 h3 = __floats2half2_rn(a[6], a[7]);
    uint4 o;
    o.x = *reinterpret_cast<unsigned*>(&h0);
    o.y = *reinterpret_cast<unsigned*>(&h1);
    o.z = *reinterpret_cast<unsigned*>(&h2);
    o.w = *reinterpret_cast<unsigned*>(&h3);
    return o;
}

__global__ __launch_bounds__(256) void spmm_gather_h(int xs)
{
    int tid = blockIdx.x * blockDim.x + threadIdx.x;
    int r = tid >> 2;
    if (r >= N_NODES) return;
    int s = tid & 3;
    const uint4* x = reinterpret_cast<const uint4*>(g_hx[xs]);
    uint4* y = reinterpret_cast<uint4*>(g_hx[xs ^ 1]);
    float acc[16];
#pragma unroll
    for (int i = 0; i < 16; i++) acc[i] = 0.f;
    spmm_row_h4(x, r, s, acc);
    y[r * 8 + 2 * s]     = pack_h8(acc);
    y[r * 8 + 2 * s + 1] = pack_h8(acc + 8);
}

// Final: out = (x0 + x1 + x2 + A*x2) / 4.  x1 = g_hx[1], x2 = g_hx[0].
__global__ __launch_bounds__(256) void spmm_final_k(float* __restrict__ out)
{
    int tid = blockIdx.x * blockDim.x + threadIdx.x;
    int r = tid >> 2;
    if (r >= N_NODES) return;
    int s = tid & 3;
    const uint4* x2 = reinterpret_cast<const uint4*>(g_hx[0]);
    const uint4* x1 = reinterpret_cast<const uint4*>(g_hx[1]);
    float acc[16];
#pragma unroll
    for (int i = 0; i < 16; i++) acc[i] = 0.f;
    spmm_row_h4(x2, r, s, acc);                        // A * x2
    acc_h(acc,     __ldg(&x1[r * 8 + 2 * s]),     1.f);    // + x1 lo
    acc_h(acc + 8, __ldg(&x1[r * 8 + 2 * s + 1]), 1.f);    // + x1 hi
    acc_h(acc,     __ldg(&x2[r * 8 + 2 * s]),     1.f);    // + x2 lo
    acc_h(acc + 8, __ldg(&x2[r * 8 + 2 * s + 1]), 1.f);    // + x2 hi
    float4* op = reinterpret_cast<float4*>(out + (size_t)r * 64 + s * 16);
#pragma unroll
    for (int i = 0; i < 4; i++) {
        float4 a = op[i];
        a.x = (a.x + acc[i * 4 + 0]) * 0.25f;
        a.y = (a.y + acc[i * 4 + 1]) * 0.25f;
        a.z = (a.z + acc[i * 4 + 2]) * 0.25f;
        a.w = (a.w + acc[i * 4 + 3]) * 0.25f;
        op[i] = a;
    }
}

// ---------------------------------------------------------------------------
extern "C" void kernel_launch(void* const* d_in, const int* in_sizes, int n_in,
                              void* d_out, int out_size)
{
    const float* user_emb    = (const float*)d_in[0];
    const float* item_emb    = (const float*)d_in[1];
    const float* gender_emb  = (const float*)d_in[2];
    const float* age_emb     = (const float*)d_in[3];
    const float* cat_emb     = (const float*)d_in[4];
    const float* bert_proj_w = (const float*)d_in[5];
    const float* item_bert   = (const float*)d_in[6];
    const float* adj_val     = (const float*)d_in[7];
    const int*   user_gender = (const int*)d_in[8];
    const int*   user_age    = (const int*)d_in[9];
    const int*   item_cat    = (const int*)d_in[10];
    const int*   adj_row     = (const int*)d_in[11];
    const int*   adj_col     = (const int*)d_in[12];
    float4* out = (float4*)d_out;

    (void)in_sizes; (void)n_in; (void)out_size;

    const int eg = (N_EDGES + 255) / 256;
    const int ng = (N_NODES + 255) / 256;

    // item_gemm stays at launch index 3 (ncu profiles index 3).
    zero_cnt_k<<<ng, 256>>>();                                     // 0
    hist_k<<<eg, 256>>>(adj_row);                                  // 1
    wfrag_k<<<96, 256>>>(bert_proj_w);                             // 2
    item_gemm_k<<<(N_ITEMS + 63) / 64, 128>>>(                     // 3 <- profiled
        item_bert, item_emb, cat_emb, item_cat, (float*)d_out);
    scan1_k<<<NB, SCAN_B>>>();                                     // 4
    scan2_k<<<1, 512>>>();                                         // 5
    scan3_k<<<ng, 256>>>();                                        // 6
    scatter_k<<<eg, 256>>>(adj_row, adj_col, adj_val);             // 7
    init_users_k<<<(N_USERS * 16 + 255) / 256, 256>>>(             // 8
        (const float4*)user_emb, (const float4*)gender_emb,
        (const float4*)age_emb, user_gender, user_age, out);

    const int sg = (N_NODES * 4 + 255) / 256;
    spmm_gather_h<<<sg, 256>>>(0);                   // x1 = A x0   (hx0 -> hx1)
    spmm_gather_h<<<sg, 256>>>(1);                   // x2 = A x1   (hx1 -> hx0)
    spmm_final_k<<<sg, 256>>>((float*)d_out);        // out = (x0+x1+x2+A x2)/4
}

// round 13
// speedup vs baseline: 1.0972x; 1.0972x over previous
#include <cuda_runtime.h>
#include <cuda_fp16.h>

#define N_USERS 200000
#define N_ITEMS 100000
#define N_NODES 300000
#define N_EDGES 1500000
#define EPAD (N_EDGES + 3 * N_NODES)   // 2,400,000 padded-edge capacity
#define DIM 64
#define BERT 384

#define SCAN_B 1024
#define NB ((N_NODES + SCAN_B - 1) / SCAN_B)   // 293

// Scratch (static device globals — no allocs).
__device__ __align__(16) __half g_hx[2][(size_t)N_NODES * DIM];  // fp16 x buffers
__device__ int   g_cnt[N_NODES];                        // degree counts -> cursors
__device__ int   g_rowptr[N_NODES + 1];
__device__ int   g_blocksum[NB];
__device__ int   g_blockoff[NB];
__device__ __align__(16) int2 g_edge[EPAD];             // {col, val bits}, padded
__device__ __align__(16) unsigned g_wfrag[24 * 1024];   // W tf32, fragment order

// ---------------------------------------------------------------------------
// CSR build: zero (cnt + edges) -> histogram -> padded 2-level scan -> scatter
// Rows are padded to a multiple of 4 edges; pad slots stay {0, 0.0f}.
// ---------------------------------------------------------------------------
__global__ void zero_all_k()
{
    int i = blockIdx.x * blockDim.x + threadIdx.x;
    if (i < N_NODES) g_cnt[i] = 0;
    if (i < EPAD / 2)
        reinterpret_cast<int4*>(g_edge)[i] = make_int4(0, 0, 0, 0);
}

__global__ void hist_k(const int* __restrict__ rows)
{
    int e = blockIdx.x * blockDim.x + threadIdx.x;
    if (e < N_EDGES) atomicAdd(&g_cnt[rows[e]], 1);
}

__global__ __launch_bounds__(SCAN_B) void scan1_k()
{
    __shared__ int wsum[32];
    int tid = threadIdx.x, lane = tid & 31, wid = tid >> 5;
    int i = blockIdx.x * SCAN_B + tid;
    int v = (i < N_NODES) ? ((g_cnt[i] + 3) & ~3) : 0;   // padded degree
    int orig = v;
#pragma unroll
    for (int d = 1; d < 32; d <<= 1) {
        int t = __shfl_up_sync(0xFFFFFFFFu, v, d);
        if (lane >= d) v += t;
    }
    if (lane == 31) wsum[wid] = v;
    __syncthreads();
    if (wid == 0) {
        int w = wsum[lane];
#pragma unroll
        for (int d = 1; d < 32; d <<= 1) {
            int t = __shfl_up_sync(0xFFFFFFFFu, w, d);
            if (lane >= d) w += t;
        }
        wsum[lane] = w;
    }
    __syncthreads();
    int woff = wid ? wsum[wid - 1] : 0;
    int incl = v + woff;
    if (i < N_NODES) g_rowptr[i] = incl - orig;                  // exclusive in-block
    if (tid == SCAN_B - 1) g_blocksum[blockIdx.x] = incl;
}

__global__ __launch_bounds__(512) void scan2_k()
{
    __shared__ int wsum[16];
    int tid = threadIdx.x, lane = tid & 31, wid = tid >> 5;
    int v = (tid < NB) ? g_blocksum[tid] : 0;
    int orig = v;
#pragma unroll
    for (int d = 1; d < 32; d <<= 1) {
        int t = __shfl_up_sync(0xFFFFFFFFu, v, d);
        if (lane >= d) v += t;
    }
    if (lane == 31) wsum[wid] = v;
    __syncthreads();
    if (wid == 0) {
        int w = (lane < 16) ? wsum[lane] : 0;
#pragma unroll
        for (int d = 1; d < 16; d <<= 1) {
            int t = __shfl_up_sync(0xFFFFFFFFu, w, d);
            if (lane >= d) w += t;
        }
        if (lane < 16) wsum[lane] = w;
    }
    __syncthreads();
    int woff = wid ? wsum[wid - 1] : 0;
    if (tid < NB) g_blockoff[tid] = v + woff - orig;             // exclusive
    if (tid == NB - 1) g_rowptr[N_NODES] = v + woff;             // padded total
}

__global__ void scan3_k()
{
    int i = blockIdx.x * blockDim.x + threadIdx.x;
    if (i < N_NODES) {
        int r = g_rowptr[i] + g_blockoff[i >> 10];
        g_rowptr[i] = r;
        g_cnt[i] = r;                                            // cursor for scatter
    }
}

__global__ void scatter_k(const int* __restrict__ rows,
                          const int* __restrict__ cols,
                          const float* __restrict__ vals)
{
    int e = blockIdx.x * blockDim.x + threadIdx.x;
    if (e >= N_EDGES) return;
    int r = rows[e];
    int p = atomicAdd(&g_cnt[r], 1);
    g_edge[p] = make_int2(cols[e], __float_as_int(vals[e]));
}

// ---------------------------------------------------------------------------
// User init: out[u] = user_emb[u] + gender + age (fp32 to d_out, fp16 to g_hx[0])
// ---------------------------------------------------------------------------
__global__ void init_users_k(const float4* __restrict__ ue,
                             const float4* __restrict__ ge,
                             const float4* __restrict__ ae,
                             const int* __restrict__ ug,
                             const int* __restrict__ ua,
                             float4* __restrict__ out)
{
    int idx = blockIdx.x * blockDim.x + threadIdx.x;
    if (idx >= N_USERS * 16) return;
    int u = idx >> 4, s = idx & 15;
    int g = ug[u];
    int a = ua[u];
    float4 r = ue[idx];
    float4 gv = ge[g * 16 + s];
    float4 av = ae[a * 16 + s];
    r.x += gv.x + av.x; r.y += gv.y + av.y;
    r.z += gv.z + av.z; r.w += gv.w + av.w;
    out[idx] = r;
    __half2 h0 = __floats2half2_rn(r.x, r.y);
    __half2 h1 = __floats2half2_rn(r.z, r.w);
    uint2 p;
    p.x = *reinterpret_cast<unsigned*>(&h0);
    p.y = *reinterpret_cast<unsigned*>(&h1);
    reinterpret_cast<uint2*>(g_hx[0])[idx] = p;
}

// ---------------------------------------------------------------------------
// TF32 GEMM with fragment-ordered smem (R10, measured 65.5us) + fp16 side copy.
// ---------------------------------------------------------------------------
#define CVT_TF32(d, s) asm("cvt.rna.tf32.f32 %0, %1;" : "=r"(d) : "f"(s))

#define MMA_TF32(c, a0, a1, a2, a3, b0, b1)                                  \
    asm("mma.sync.aligned.m16n8k8.row.col.f32.tf32.tf32.f32 "               \
        "{%0,%1,%2,%3}, {%4,%5,%6,%7}, {%8,%9}, {%0,%1,%2,%3};"             \
        : "+f"((c)[0]), "+f"((c)[1]), "+f"((c)[2]), "+f"((c)[3])            \
        : "r"(a0), "r"(a1), "r"(a2), "r"(a3), "r"(b0), "r"(b1))

__global__ void wfrag_k(const float* __restrict__ W)
{
    int w = blockIdx.x * 256 + threadIdx.x;
    if (w >= 24 * 1024) return;
    int kt = w >> 10, r = w & 1023;
    int ipair = r >> 7;              // kk*4 + ntp
    int kk = ipair >> 2, ntp = ipair & 3;
    int r2 = r & 127;
    int lane = r2 >> 2, low = r2 & 3;
    int nthalf = low >> 1, reg = low & 1;
    int nt = ntp * 2 + nthalf;
    int gid = lane >> 2, tig = lane & 3;
    int n = nt * 8 + gid;
    int k = kt * 16 + kk * 8 + tig + reg * 4;
    unsigned u;
    CVT_TF32(u, W[(size_t)n * BERT + k]);
    g_wfrag[w] = u;
}

#define NKT (BERT / 16)     // 24
#define APAD 20

__global__ __launch_bounds__(128) void item_gemm_k(
    const float* __restrict__ bert,      // [N_ITEMS, 384]
    const float* __restrict__ ie,        // item_emb [N_ITEMS, 64]
    const float* __restrict__ ce,        // cat_emb [11, 64]
    const int* __restrict__ cat,
    float* __restrict__ out)
{
    __shared__ __align__(16) unsigned As[2][64 * APAD];   // [buf][m*20 + k]
    __shared__ __align__(16) uint4    Bs[2][256];          // [buf] fragment order

    int t    = threadIdx.x;
    int wid  = t >> 5;
    int lane = t & 31;
    int gid  = lane >> 2;        // 0..7
    int tig  = lane & 3;         // 0..3
    int wrow = wid * 16;
    int rb   = blockIdx.x * 64;

    float c[8][4];
#pragma unroll
    for (int nt = 0; nt < 8; nt++)
#pragma unroll
        for (int j = 0; j < 4; j++) c[nt][j] = 0.f;

    const uint4* wsrc = reinterpret_cast<const uint4*>(g_wfrag);
    float4 va[2];
    uint4  vb[2];

#define LOAD_AB(k0, kt)                                                      \
    {                                                                        \
        _Pragma("unroll")                                                    \
        for (int i = 0; i < 2; i++) {                                        \
            int q = i * 128 + t;                                             \
            int m = q >> 2, kq = q & 3;                                      \
            va[i] = (rb + m < N_ITEMS)                                       \
                ? *reinterpret_cast<const float4*>(                          \
                      bert + (size_t)(rb + m) * BERT + (k0) + kq * 4)        \
                : make_float4(0.f, 0.f, 0.f, 0.f);                           \
            vb[i] = __ldg(wsrc + (kt) * 256 + i * 128 + t);                  \
        }                                                                    \
    }
#define STORE_AB(buf)                                                        \
    {                                                                        \
        _Pragma("unroll")                                                    \
        for (int i = 0; i < 2; i++) {                                        \
            int q = i * 128 + t;                                             \
            int m = q >> 2, kq = q & 3;                                      \
            unsigned u0, u1, u2, u3;                                         \
            CVT_TF32(u0, va[i].x); CVT_TF32(u1, va[i].y);                    \
            CVT_TF32(u2, va[i].z); CVT_TF32(u3, va[i].w);                    \
            *reinterpret_cast<uint4*>(&As[buf][m * APAD + kq * 4]) =         \
                make_uint4(u0, u1, u2, u3);                                  \
            Bs[buf][i * 128 + t] = vb[i];                                    \
        }                                                                    \
    }

    LOAD_AB(0, 0);
    STORE_AB(0);
    __syncthreads();

#pragma unroll 1
    for (int kt = 0; kt < NKT; kt++) {
        int buf = kt & 1;
        if (kt + 1 < NKT) LOAD_AB((kt + 1) * 16, kt + 1);

#pragma unroll
        for (int kk = 0; kk < 2; kk++) {
            int kb = kk * 8;
            unsigned a0 = As[buf][(wrow + gid)     * APAD + kb + tig];
            unsigned a1 = As[buf][(wrow + gid + 8) * APAD + kb + tig];
            unsigned a2 = As[buf][(wrow + gid)     * APAD + kb + tig + 4];
            unsigned a3 = As[buf][(wrow + gid + 8) * APAD + kb + tig + 4];
#pragma unroll
            for (int ntp = 0; ntp < 4; ntp++) {
                uint4 bb = Bs[buf][(kk * 4 + ntp) * 32 + lane];
                MMA_TF32(c[2 * ntp],     a0, a1, a2, a3, bb.x, bb.y);
                MMA_TF32(c[2 * ntp + 1], a0, a1, a2, a3, bb.z, bb.w);
            }
        }

        if (kt + 1 < NKT) STORE_AB(buf ^ 1);
        __syncthreads();
    }

    // Epilogue: + item_emb + cat_emb; fp32 to out, fp16 copy to g_hx[0].
    int r0 = rb + wrow + gid;
    int r1 = r0 + 8;
    int cc0 = (r0 < N_ITEMS) ? cat[r0] : 0;
    int cc1 = (r1 < N_ITEMS) ? cat[r1] : 0;
    __half* hx0 = g_hx[0];
#pragma unroll
    for (int nt = 0; nt < 8; nt++) {
        int n0 = nt * 8 + tig * 2;
        if (r0 < N_ITEMS) {
            float2 e = *reinterpret_cast<const float2*>(ie + (size_t)r0 * 64 + n0);
            float2 v = *reinterpret_cast<const float2*>(ce + (size_t)cc0 * 64 + n0);
            float2 o = make_float2(c[nt][0] + e.x + v.x, c[nt][1] + e.y + v.y);
            *reinterpret_cast<float2*>(out + (size_t)(N_USERS + r0) * 64 + n0) = o;
            __half2 h = __floats2half2_rn(o.x, o.y);
            *reinterpret_cast<unsigned*>(hx0 + (size_t)(N_USERS + r0) * 64 + n0) =
                *reinterpret_cast<unsigned*>(&h);
        }
        if (r1 < N_ITEMS) {
            float2 e = *reinterpret_cast<const float2*>(ie + (size_t)r1 * 64 + n0);
            float2 v = *reinterpret_cast<const float2*>(ce + (size_t)cc1 * 64 + n0);
            float2 o = make_float2(c[nt][2] + e.x + v.x, c[nt][3] + e.y + v.y);
            *reinterpret_cast<float2*>(out + (size_t)(N_USERS + r1) * 64 + n0) = o;
            __half2 h = __floats2half2_rn(o.x, o.y);
            *reinterpret_cast<unsigned*>(hx0 + (size_t)(N_USERS + r1) * 64 + n0) =
                *reinterpret_cast<unsigned*>(&h);
        }
    }
}

// ---------------------------------------------------------------------------
// CSR gather SpMM on fp16 features (R11 8-lane shape, uniform control flow):
// rows padded to multiples of 4 edges -> single branch-free 4-edge rung.
// Edge records load as 2x int4 (beg is 16B-aligned).  Per edge per lane:
// 1 LDG.128 + 4 cvt + 8 FMA.  Compute fp32, store fp16.
// ---------------------------------------------------------------------------
__device__ __forceinline__ void acc_h(float* a, uint4 xv, float v)
{
    float2 f0 = __half22float2(*reinterpret_cast<__half2*>(&xv.x));
    float2 f1 = __half22float2(*reinterpret_cast<__half2*>(&xv.y));
    float2 f2 = __half22float2(*reinterpret_cast<__half2*>(&xv.z));
    float2 f3 = __half22float2(*reinterpret_cast<__half2*>(&xv.w));
    a[0] += v * f0.x; a[1] += v * f0.y;
    a[2] += v * f1.x; a[3] += v * f1.y;
    a[4] += v * f2.x; a[5] += v * f2.y;
    a[6] += v * f3.x; a[7] += v * f3.y;
}

__device__ __forceinline__ void spmm_row_h(const uint4* __restrict__ x,
                                           int r, int s, float* acc)
{
    int beg = __ldg(&g_rowptr[r]);
    int end = __ldg(&g_rowptr[r + 1]);
#pragma unroll 1
    for (int jj = beg; jj < end; jj += 4) {
        int4 eA = __ldg(reinterpret_cast<const int4*>(g_edge + jj));
        int4 eB = __ldg(reinterpret_cast<const int4*>(g_edge + jj + 2));
        uint4 x0 = __ldg(&x[eA.x * 8 + s]);
        uint4 x1 = __ldg(&x[eA.z * 8 + s]);
        uint4 x2 = __ldg(&x[eB.x * 8 + s]);
        uint4 x3 = __ldg(&x[eB.z * 8 + s]);
        acc_h(acc, x0, __int_as_float(eA.y));
        acc_h(acc, x1, __int_as_float(eA.w));
        acc_h(acc, x2, __int_as_float(eB.y));
        acc_h(acc, x3, __int_as_float(eB.w));
    }
}

__device__ __forceinline__ uint4 pack_h8(const float* a)
{
    __half2 h0 = __floats2half2_rn(a[0], a[1]);
    __half2 h1 = __floats2half2_rn(a[2], a[3]);
    __half2 h2 = __floats2half2_rn(a[4], a[5]);
    __half2 h3 = __floats2half2_rn(a[6], a[7]);
    uint4 o;
    o.x = *reinterpret_cast<unsigned*>(&h0);
    o.y = *reinterpret_cast<unsigned*>(&h1);
    o.z = *reinterpret_cast<unsigned*>(&h2);
    o.w = *reinterpret_cast<unsigned*>(&h3);
    return o;
}

__global__ __launch_bounds__(256) void spmm_gather_h(int xs)
{
    int tid = blockIdx.x * blockDim.x + threadIdx.x;
    int r = tid >> 3;
    if (r >= N_NODES) return;
    int s = tid & 7;
    const uint4* x = reinterpret_cast<const uint4*>(g_hx[xs]);
    uint4* y = reinterpret_cast<uint4*>(g_hx[xs ^ 1]);
    float acc[8] = {0.f, 0.f, 0.f, 0.f, 0.f, 0.f, 0.f, 0.f};
    spmm_row_h(x, r, s, acc);
    y[r * 8 + s] = pack_h8(acc);
}

// Final: out = (x0 + x1 + x2 + A*x2) / 4.  x1 = g_hx[1], x2 = g_hx[0].
__global__ __launch_bounds__(256) void spmm_final_k(float* __restrict__ out)
{
    int tid = blockIdx.x * blockDim.x + threadIdx.x;
    int r = tid >> 3;
    if (r >= N_NODES) return;
    int s = tid & 7;
    const uint4* x2 = reinterpret_cast<const uint4*>(g_hx[0]);
    const uint4* x1 = reinterpret_cast<const uint4*>(g_hx[1]);
    float acc[8] = {0.f, 0.f, 0.f, 0.f, 0.f, 0.f, 0.f, 0.f};
    spmm_row_h(x2, r, s, acc);                    // A * x2
    acc_h(acc, __ldg(&x1[r * 8 + s]), 1.f);       // + x1
    acc_h(acc, __ldg(&x2[r * 8 + s]), 1.f);       // + x2
    float4* op = reinterpret_cast<float4*>(out + (size_t)r * 64 + s * 8);
    float4 a0 = op[0];
    float4 a1 = op[1];
    a0.x = (a0.x + acc[0]) * 0.25f; a0.y = (a0.y + acc[1]) * 0.25f;
    a0.z = (a0.z + acc[2]) * 0.25f; a0.w = (a0.w + acc[3]) * 0.25f;
    a1.x = (a1.x + acc[4]) * 0.25f; a1.y = (a1.y + acc[5]) * 0.25f;
    a1.z = (a1.z + acc[6]) * 0.25f; a1.w = (a1.w + acc[7]) * 0.25f;
    op[0] = a0;
    op[1] = a1;
}

// ---------------------------------------------------------------------------
extern "C" void kernel_launch(void* const* d_in, const int* in_sizes, int n_in,
                              void* d_out, int out_size)
{
    const float* user_emb    = (const float*)d_in[0];
    const float* item_emb    = (const float*)d_in[1];
    const float* gender_emb  = (const float*)d_in[2];
    const float* age_emb     = (const float*)d_in[3];
    const float* cat_emb     = (const float*)d_in[4];
    const float* bert_proj_w = (const float*)d_in[5];
    const float* item_bert   = (const float*)d_in[6];
    const float* adj_val     = (const float*)d_in[7];
    const int*   user_gender = (const int*)d_in[8];
    const int*   user_age    = (const int*)d_in[9];
    const int*   item_cat    = (const int*)d_in[10];
    const int*   adj_row     = (const int*)d_in[11];
    const int*   adj_col     = (const int*)d_in[12];
    float4* out = (float4*)d_out;

    (void)in_sizes; (void)n_in; (void)out_size;

    const int eg = (N_EDGES + 255) / 256;
    const int zg = (EPAD / 2 + 255) / 256;
    const int ng = (N_NODES + 255) / 256;

    // item_gemm stays at launch index 3 (ncu profiles index 3).
    zero_all_k<<<zg, 256>>>();                                     // 0
    hist_k<<<eg, 256>>>(adj_row);                                  // 1
    wfrag_k<<<96, 256>>>(bert_proj_w);                             // 2
    item_gemm_k<<<(N_ITEMS + 63) / 64, 128>>>(                     // 3 <- profiled
        item_bert, item_emb, cat_emb, item_cat, (float*)d_out);
    scan1_k<<<NB, SCAN_B>>>();                                     // 4
    scan2_k<<<1, 512>>>();                                         // 5
    scan3_k<<<ng, 256>>>();                                        // 6
    scatter_k<<<eg, 256>>>(adj_row, adj_col, adj_val);             // 7
    init_users_k<<<(N_USERS * 16 + 255) / 256, 256>>>(             // 8
        (const float4*)user_emb, (const float4*)gender_emb,
        (const float4*)age_emb, user_gender, user_age, out);

    const int sg = (N_NODES * 8 + 255) / 256;
    spmm_gather_h<<<sg, 256>>>(0);                   // x1 = A x0   (hx0 -> hx1)
    spmm_gather_h<<<sg, 256>>>(1);                   // x2 = A x1   (hx1 -> hx0)
    spmm_final_k<<<sg, 256>>>((float*)d_out);        // out = (x0+x1+x2+A x2)/4
}